// round 11
// baseline (speedup 1.0000x reference)
#include <cuda_runtime.h>
#include <stdint.h>

#define VOCAB 30000
#define D     768
#define L     512
#define K1    1.2f
#define BPAR  0.75f

// Scratch (static __device__ globals — no runtime allocation per harness rule).
__device__ float g_Wt[(size_t)VOCAB * D];   // 92.16 MB transposed weights
__device__ float g_colsum[D];
__device__ int   g_is64;                    // 1 if ids/mask are int64, 0 if int32

// ---------------------------------------------------------------------------
// Kernel 0: detect ids dtype. int64 values < 30000 have all-zero high words;
// int32 token data has nonzero odd words with overwhelming probability.
// ---------------------------------------------------------------------------
__global__ void detect_kernel(const int* __restrict__ ids_words) {
    if (threadIdx.x == 0 && blockIdx.x == 0) {
        int acc = 0;
        #pragma unroll
        for (int i = 0; i < 128; i += 2) acc |= ids_words[i + 1];
        g_is64 = (acc == 0) ? 1 : 0;
    }
}

// ---------------------------------------------------------------------------
// Kernel 1: transpose W [D, VOCAB] row-major -> g_Wt [VOCAB, D] row-major.
// ---------------------------------------------------------------------------
__global__ void transpose_kernel(const float* __restrict__ W) {
    __shared__ float tile[32][33];
    const int t0 = blockIdx.x * 32;
    const int d0 = blockIdx.y * 32;
    const int tx = threadIdx.x;
    const int ty = threadIdx.y;

    #pragma unroll
    for (int k = 0; k < 32; k += 8) {
        const int d = d0 + ty + k;
        const int t = t0 + tx;
        tile[ty + k][tx] = (t < VOCAB) ? W[(size_t)d * VOCAB + t] : 0.0f;
    }
    __syncthreads();
    #pragma unroll
    for (int k = 0; k < 32; k += 8) {
        const int t = t0 + ty + k;
        const int d = d0 + tx;
        if (t < VOCAB) g_Wt[(size_t)t * D + d] = tile[tx][ty + k];
    }
}

// ---------------------------------------------------------------------------
// Kernel 2: colsum[d] = sum_t W[d, t].  One block per d, float4 row reduce.
// ---------------------------------------------------------------------------
__global__ void colsum_kernel(const float* __restrict__ W) {
    const int d = blockIdx.x;
    const float4* row = (const float4*)(W + (size_t)d * VOCAB);
    float s = 0.0f;
    for (int t = threadIdx.x; t < VOCAB / 4; t += 256) {
        const float4 v = row[t];
        s += (v.x + v.y) + (v.z + v.w);
    }
    #pragma unroll
    for (int o = 16; o > 0; o >>= 1) s += __shfl_down_sync(0xFFFFFFFFu, s, o);
    __shared__ float red[8];
    if ((threadIdx.x & 31) == 0) red[threadIdx.x >> 5] = s;
    __syncthreads();
    if (threadIdx.x == 0) {
        float tot = 0.0f;
        #pragma unroll
        for (int i = 0; i < 8; i++) tot += red[i];
        g_colsum[d] = tot;
    }
}

// ---------------------------------------------------------------------------
// Kernel 3: per-row BM25 score + sparse gather-matvec + L2-normalize.
// One block (256 threads) per batch row.
// ---------------------------------------------------------------------------
__global__ __launch_bounds__(256) void bm25_kernel(
    const void* __restrict__ ids_raw,
    const void* __restrict__ mask_raw,
    float* __restrict__ out)
{
    __shared__ int   s_tok[L];
    __shared__ int   s_ct[L];
    __shared__ float s_cs[L];
    __shared__ int   s_nvalid;
    __shared__ float s_red[6];
    __shared__ float s_rnorm;

    const int b   = blockIdx.x;
    const int tid = threadIdx.x;

    if (tid == 0) s_nvalid = 0;
    __syncthreads();

    // ---- phase 1: load tokens (dtype-dispatched), validity, doc_len ----
    int myvalid = 0;
    if (g_is64) {
        const longlong2* id2 = (const longlong2*)((const long long*)ids_raw  + (size_t)b * L);
        const longlong2* mk2 = (const longlong2*)((const long long*)mask_raw + (size_t)b * L);
        const longlong2 iv = id2[tid];
        const longlong2 mv = mk2[tid];
        const bool v0 = (mv.x == 1) && (iv.x > 100) && (iv.x < VOCAB);
        const bool v1 = (mv.y == 1) && (iv.y > 100) && (iv.y < VOCAB);
        s_tok[tid * 2 + 0] = v0 ? (int)iv.x : -1;
        s_tok[tid * 2 + 1] = v1 ? (int)iv.y : -1;
        myvalid = (v0 ? 1 : 0) + (v1 ? 1 : 0);
    } else {
        const int2* id2 = (const int2*)((const int*)ids_raw  + (size_t)b * L);
        const int2* mk2 = (const int2*)((const int*)mask_raw + (size_t)b * L);
        const int2 iv = id2[tid];
        const int2 mv = mk2[tid];
        const bool v0 = (mv.x == 1) && (iv.x > 100) && (iv.x < VOCAB);
        const bool v1 = (mv.y == 1) && (iv.y > 100) && (iv.y < VOCAB);
        s_tok[tid * 2 + 0] = v0 ? iv.x : -1;
        s_tok[tid * 2 + 1] = v1 ? iv.y : -1;
        myvalid = (v0 ? 1 : 0) + (v1 ? 1 : 0);
    }
    #pragma unroll
    for (int o = 16; o > 0; o >>= 1) myvalid += __shfl_down_sync(0xFFFFFFFFu, myvalid, o);
    if ((tid & 31) == 0) atomicAdd(&s_nvalid, myvalid);
    __syncthreads();

    const float doc_len = (float)s_nvalid;
    const float lnorm   = fmaxf(1.0f + BPAR * (doc_len * 0.01f - 1.0f), 0.5f);

    // ---- phase 2: tf + first occurrence, one pass over j for both i-slots ----
    {
        const int i0 = tid;
        const int i1 = tid + 256;
        const int t0 = s_tok[i0];
        const int t1 = s_tok[i1];
        int c0 = 0, c1 = 0, m0 = L, m1 = L;
        #pragma unroll 8
        for (int j = 0; j < L; j++) {
            const int tj = s_tok[j];           // uniform address -> LDS broadcast
            if (tj == t0) { c0++; m0 = min(m0, j); }
            if (tj == t1) { c1++; m1 = min(m1, j); }
        }
        float sc0 = 0.0f, sc1 = 0.0f;
        int   ct0 = 0,    ct1 = 0;
        if (t0 >= 0 && m0 == i0) {
            const float tf = (float)c0;
            sc0 = tf * (K1 + 1.0f) / (tf + K1 * lnorm);
            ct0 = t0;
        }
        if (t1 >= 0 && m1 == i1) {
            const float tf = (float)c1;
            sc1 = tf * (K1 + 1.0f) / (tf + K1 * lnorm);
            ct1 = t1;
        }
        s_cs[i0] = sc0; s_ct[i0] = ct0;
        s_cs[i1] = sc1; s_ct[i1] = ct1;
    }
    __syncthreads();

    // ---- phase 3: gather-accumulate; 192 threads, thread t owns dims [4t,4t+4) ----
    float4 acc = make_float4(0.f, 0.f, 0.f, 0.f);
    if (tid < 192) {
        const float4 cs4 = *(const float4*)(g_colsum + tid * 4);
        acc.x = 1e-10f * cs4.x;
        acc.y = 1e-10f * cs4.y;
        acc.z = 1e-10f * cs4.z;
        acc.w = 1e-10f * cs4.w;

        #pragma unroll 1
        for (int i = 0; i < L; i += 8) {
            float  c[8];
            float4 x[8];
            #pragma unroll
            for (int k = 0; k < 8; k++) {
                c[k] = s_cs[i + k];
                x[k] = *((const float4*)(g_Wt + (size_t)s_ct[i + k] * D) + tid);
            }
            #pragma unroll
            for (int k = 0; k < 8; k++) {
                acc.x = fmaf(c[k], x[k].x, acc.x);
                acc.y = fmaf(c[k], x[k].y, acc.y);
                acc.z = fmaf(c[k], x[k].z, acc.z);
                acc.w = fmaf(c[k], x[k].w, acc.w);
            }
        }
    }

    // ---- phase 4: row L2 norm over 768 dims, then store ----
    float sq = acc.x * acc.x + acc.y * acc.y + acc.z * acc.z + acc.w * acc.w;
    #pragma unroll
    for (int o = 16; o > 0; o >>= 1) sq += __shfl_down_sync(0xFFFFFFFFu, sq, o);
    if (tid < 192 && (tid & 31) == 0) s_red[tid >> 5] = sq;
    __syncthreads();
    if (tid == 0) {
        float tot = 0.0f;
        #pragma unroll
        for (int i = 0; i < 6; i++) tot += s_red[i];
        s_rnorm = rsqrtf(tot);
    }
    __syncthreads();
    if (tid < 192) {
        const float rn = s_rnorm;
        float4 r;
        r.x = acc.x * rn; r.y = acc.y * rn; r.z = acc.z * rn; r.w = acc.w * rn;
        *((float4*)(out + (size_t)b * D) + tid) = r;
    }
}

// ---------------------------------------------------------------------------
extern "C" void kernel_launch(void* const* d_in, const int* in_sizes, int n_in,
                              void* d_out, int out_size) {
    // Identify W by element count (768*30000 = 23,040,000); the remaining two
    // inputs, in order, are input_ids and attention_mask.
    int wi = -1;
    for (int i = 0; i < n_in; i++)
        if (in_sizes[i] == VOCAB * D) { wi = i; break; }
    if (wi < 0) wi = 2;   // fallback: metadata order (ids, mask, W)

    int idx_ids = -1, idx_mask = -1;
    for (int i = 0; i < n_in; i++) {
        if (i == wi) continue;
        if (idx_ids < 0) idx_ids = i;
        else if (idx_mask < 0) idx_mask = i;
    }

    const void*  ids  = d_in[idx_ids];
    const void*  mask = d_in[idx_mask];
    const float* W    = (const float*)d_in[wi];
    float*       out  = (float*)d_out;

    const int B = in_sizes[idx_ids] / L;

    detect_kernel<<<1, 32>>>((const int*)ids);
    dim3 tgrid((VOCAB + 31) / 32, D / 32);
    transpose_kernel<<<tgrid, dim3(32, 8)>>>(W);
    colsum_kernel<<<D, 256>>>(W);
    bm25_kernel<<<B, 256>>>(ids, mask, out);
}

// round 12
// speedup vs baseline: 1.1422x; 1.1422x over previous
#include <cuda_runtime.h>
#include <cuda_fp16.h>
#include <stdint.h>

#define VOCAB 30000
#define D     768
#define L     512
#define K1    1.2f
#define BPAR  0.75f

// Scratch (static __device__ globals — no runtime allocation per harness rule).
__device__ __half g_Wth[(size_t)VOCAB * D]; // 46.08 MB transposed weights, fp16
__device__ float  g_colsum[D];              // exact fp32 column sums
__device__ int    g_is64;                   // 1 if ids/mask are int64, 0 if int32

// ---------------------------------------------------------------------------
// Kernel 0: detect ids dtype. int64 values < 30000 have all-zero high words;
// int32 token data has nonzero odd words with overwhelming probability.
// ---------------------------------------------------------------------------
__global__ void detect_kernel(const int* __restrict__ ids_words) {
    if (threadIdx.x == 0 && blockIdx.x == 0) {
        int acc = 0;
        #pragma unroll
        for (int i = 0; i < 128; i += 2) acc |= ids_words[i + 1];
        g_is64 = (acc == 0) ? 1 : 0;
    }
}

// ---------------------------------------------------------------------------
// Kernel 1: transpose W [D, VOCAB] fp32 -> g_Wth [VOCAB, D] fp16.
// 32x32 tiles via shared memory, both global accesses coalesced.
// ---------------------------------------------------------------------------
__global__ void transpose_kernel(const float* __restrict__ W) {
    __shared__ float tile[32][33];
    const int t0 = blockIdx.x * 32;
    const int d0 = blockIdx.y * 32;
    const int tx = threadIdx.x;
    const int ty = threadIdx.y;

    #pragma unroll
    for (int k = 0; k < 32; k += 8) {
        const int d = d0 + ty + k;
        const int t = t0 + tx;
        tile[ty + k][tx] = (t < VOCAB) ? W[(size_t)d * VOCAB + t] : 0.0f;
    }
    __syncthreads();
    #pragma unroll
    for (int k = 0; k < 32; k += 8) {
        const int t = t0 + ty + k;
        const int d = d0 + tx;
        if (t < VOCAB) g_Wth[(size_t)t * D + d] = __float2half_rn(tile[tx][ty + k]);
    }
}

// ---------------------------------------------------------------------------
// Kernel 2: colsum[d] = sum_t W[d, t] in fp32.  One block per d.
// ---------------------------------------------------------------------------
__global__ void colsum_kernel(const float* __restrict__ W) {
    const int d = blockIdx.x;
    const float4* row = (const float4*)(W + (size_t)d * VOCAB);
    float s = 0.0f;
    for (int t = threadIdx.x; t < VOCAB / 4; t += 256) {
        const float4 v = row[t];
        s += (v.x + v.y) + (v.z + v.w);
    }
    #pragma unroll
    for (int o = 16; o > 0; o >>= 1) s += __shfl_down_sync(0xFFFFFFFFu, s, o);
    __shared__ float red[8];
    if ((threadIdx.x & 31) == 0) red[threadIdx.x >> 5] = s;
    __syncthreads();
    if (threadIdx.x == 0) {
        float tot = 0.0f;
        #pragma unroll
        for (int i = 0; i < 8; i++) tot += red[i];
        g_colsum[d] = tot;
    }
}

// ---------------------------------------------------------------------------
// Kernel 3: per-row BM25 score + sparse fp16 gather-matvec + L2-normalize.
// One block (256 threads) per batch row.
// ---------------------------------------------------------------------------
__global__ __launch_bounds__(256) void bm25_kernel(
    const void* __restrict__ ids_raw,
    const void* __restrict__ mask_raw,
    float* __restrict__ out)
{
    __shared__ int   s_tok[L];
    __shared__ int   s_ct[L];
    __shared__ float s_cs[L];
    __shared__ int   s_nvalid;
    __shared__ float s_red[6];
    __shared__ float s_rnorm;

    const int b   = blockIdx.x;
    const int tid = threadIdx.x;

    if (tid == 0) s_nvalid = 0;
    __syncthreads();

    // ---- phase 1: load tokens (dtype-dispatched), validity, doc_len ----
    int myvalid = 0;
    if (g_is64) {
        const longlong2* id2 = (const longlong2*)((const long long*)ids_raw  + (size_t)b * L);
        const longlong2* mk2 = (const longlong2*)((const long long*)mask_raw + (size_t)b * L);
        const longlong2 iv = id2[tid];
        const longlong2 mv = mk2[tid];
        const bool v0 = (mv.x == 1) && (iv.x > 100) && (iv.x < VOCAB);
        const bool v1 = (mv.y == 1) && (iv.y > 100) && (iv.y < VOCAB);
        s_tok[tid * 2 + 0] = v0 ? (int)iv.x : -1;
        s_tok[tid * 2 + 1] = v1 ? (int)iv.y : -1;
        myvalid = (v0 ? 1 : 0) + (v1 ? 1 : 0);
    } else {
        const int2* id2 = (const int2*)((const int*)ids_raw  + (size_t)b * L);
        const int2* mk2 = (const int2*)((const int*)mask_raw + (size_t)b * L);
        const int2 iv = id2[tid];
        const int2 mv = mk2[tid];
        const bool v0 = (mv.x == 1) && (iv.x > 100) && (iv.x < VOCAB);
        const bool v1 = (mv.y == 1) && (iv.y > 100) && (iv.y < VOCAB);
        s_tok[tid * 2 + 0] = v0 ? iv.x : -1;
        s_tok[tid * 2 + 1] = v1 ? iv.y : -1;
        myvalid = (v0 ? 1 : 0) + (v1 ? 1 : 0);
    }
    #pragma unroll
    for (int o = 16; o > 0; o >>= 1) myvalid += __shfl_down_sync(0xFFFFFFFFu, myvalid, o);
    if ((tid & 31) == 0) atomicAdd(&s_nvalid, myvalid);
    __syncthreads();

    const float doc_len = (float)s_nvalid;
    const float lnorm   = fmaxf(1.0f + BPAR * (doc_len * 0.01f - 1.0f), 0.5f);

    // ---- phase 2: tf + first occurrence, one pass over j for both i-slots ----
    {
        const int i0 = tid;
        const int i1 = tid + 256;
        const int t0 = s_tok[i0];
        const int t1 = s_tok[i1];
        int c0 = 0, c1 = 0, m0 = L, m1 = L;
        #pragma unroll 8
        for (int j = 0; j < L; j++) {
            const int tj = s_tok[j];           // uniform address -> LDS broadcast
            if (tj == t0) { c0++; m0 = min(m0, j); }
            if (tj == t1) { c1++; m1 = min(m1, j); }
        }
        float sc0 = 0.0f, sc1 = 0.0f;
        int   ct0 = 0,    ct1 = 0;
        if (t0 >= 0 && m0 == i0) {
            const float tf = (float)c0;
            sc0 = tf * (K1 + 1.0f) / (tf + K1 * lnorm);
            ct0 = t0;
        }
        if (t1 >= 0 && m1 == i1) {
            const float tf = (float)c1;
            sc1 = tf * (K1 + 1.0f) / (tf + K1 * lnorm);
            ct1 = t1;
        }
        s_cs[i0] = sc0; s_ct[i0] = ct0;
        s_cs[i1] = sc1; s_ct[i1] = ct1;
    }
    __syncthreads();

    // ---- phase 3: fp16 gather-accumulate; 192 threads own dims [4t,4t+4) ----
    float4 acc = make_float4(0.f, 0.f, 0.f, 0.f);
    if (tid < 192) {
        const float4 cs4 = *(const float4*)(g_colsum + tid * 4);
        acc.x = 1e-10f * cs4.x;
        acc.y = 1e-10f * cs4.y;
        acc.z = 1e-10f * cs4.z;
        acc.w = 1e-10f * cs4.w;

        #pragma unroll 1
        for (int i = 0; i < L; i += 8) {
            // 8 independent LDG.64 in flight, then unpack + 32 FMAs.
            float c[8];
            uint2 u[8];
            #pragma unroll
            for (int k = 0; k < 8; k++) {
                c[k] = s_cs[i + k];
                u[k] = *((const uint2*)(g_Wth + (size_t)s_ct[i + k] * D) + tid);
            }
            #pragma unroll
            for (int k = 0; k < 8; k++) {
                const float2 f0 = __half22float2(*(const __half2*)&u[k].x);
                const float2 f1 = __half22float2(*(const __half2*)&u[k].y);
                acc.x = fmaf(c[k], f0.x, acc.x);
                acc.y = fmaf(c[k], f0.y, acc.y);
                acc.z = fmaf(c[k], f1.x, acc.z);
                acc.w = fmaf(c[k], f1.y, acc.w);
            }
        }
    }

    // ---- phase 4: row L2 norm over 768 dims, then store ----
    float sq = acc.x * acc.x + acc.y * acc.y + acc.z * acc.z + acc.w * acc.w;
    #pragma unroll
    for (int o = 16; o > 0; o >>= 1) sq += __shfl_down_sync(0xFFFFFFFFu, sq, o);
    if (tid < 192 && (tid & 31) == 0) s_red[tid >> 5] = sq;
    __syncthreads();
    if (tid == 0) {
        float tot = 0.0f;
        #pragma unroll
        for (int i = 0; i < 6; i++) tot += s_red[i];
        s_rnorm = rsqrtf(tot);
    }
    __syncthreads();
    if (tid < 192) {
        const float rn = s_rnorm;
        float4 r;
        r.x = acc.x * rn; r.y = acc.y * rn; r.z = acc.z * rn; r.w = acc.w * rn;
        *((float4*)(out + (size_t)b * D) + tid) = r;
    }
}

// ---------------------------------------------------------------------------
extern "C" void kernel_launch(void* const* d_in, const int* in_sizes, int n_in,
                              void* d_out, int out_size) {
    // Identify W by element count (768*30000); remaining two are ids, mask.
    int wi = -1;
    for (int i = 0; i < n_in; i++)
        if (in_sizes[i] == VOCAB * D) { wi = i; break; }
    if (wi < 0) wi = 2;

    int idx_ids = -1, idx_mask = -1;
    for (int i = 0; i < n_in; i++) {
        if (i == wi) continue;
        if (idx_ids < 0) idx_ids = i;
        else if (idx_mask < 0) idx_mask = i;
    }

    const void*  ids  = d_in[idx_ids];
    const void*  mask = d_in[idx_mask];
    const float* W    = (const float*)d_in[wi];
    float*       out  = (float*)d_out;

    const int B = in_sizes[idx_ids] / L;

    detect_kernel<<<1, 32>>>((const int*)ids);
    dim3 tgrid((VOCAB + 31) / 32, D / 32);
    transpose_kernel<<<tgrid, dim3(32, 8)>>>(W);
    colsum_kernel<<<D, 256>>>(W);
    bm25_kernel<<<B, 256>>>(ids, mask, out);
}